// round 10
// baseline (speedup 1.0000x reference)
#include <cuda_runtime.h>
#include <cuda_bf16.h>
#include <cuda_fp16.h>

#define NB   2
#define NC   128
#define NH   64
#define NW   512
#define NHW  32768
#define EPSF 1e-5f
#define NEGF (-1.0e30f)

// ---------------- scratch (device globals) ----------------------------------
__device__ uint2  g_arrBh[NB * 32 * NHW];  // maskfold(T) fp16x4  [b][og][p]
__device__ __align__(16) __half g_Whi16[NC * NC];
__device__ __align__(16) __half g_Wlo16[NC * NC];
__device__ float  g_fshift[NC];
__device__ float  g_pws[NC * 3];
__device__ float  g_pshift[NC];
__device__ float  g_escale[4];
__device__ float  g_eshift[4];
__device__ float  g_maskF[NB * NHW];
__device__ int    g_maskMode;

// ---------------- prep + mask dtype detection (merged) -----------------------
__global__ void prep_kernel(const float* __restrict__ fw, const float* __restrict__ fg,
                            const float* __restrict__ fb_, const float* __restrict__ fm,
                            const float* __restrict__ fv, const float* __restrict__ pw,
                            const float* __restrict__ pg, const float* __restrict__ pb_,
                            const float* __restrict__ pm, const float* __restrict__ pv,
                            const float* __restrict__ eg, const float* __restrict__ eb_,
                            const float* __restrict__ em, const float* __restrict__ ev,
                            const unsigned int* __restrict__ mraw) {
    if (blockIdx.x == 64) {
        __shared__ unsigned int fl;
        int t = threadIdx.x;
        if (t == 0) fl = 0;
        __syncthreads();
        unsigned int flags = 0;
        for (int k = t; k < 1024; k += 256) {
            unsigned int x = mraw[k];
            if (x == 0u) continue;
            unsigned int lo = x & 0xFFFFu, hi = x >> 16;
            if (x == 0x3F800000u) flags |= 1u;
            bool blo = (lo == 0u || lo == 0x3F80u), bhi = (hi == 0u || hi == 0x3F80u);
            bool hlo = (lo == 0u || lo == 0x3C00u), hhi = (hi == 0u || hi == 0x3C00u);
            if (blo && bhi && x != 0x3F800000u) flags |= 8u;
            else if (hlo && hhi) flags |= 16u;
            else if ((x & 0xFEFEFEFEu) == 0u) {
                if (x & 0xFFFFFF00u) flags |= 2u;
                else flags |= 4u;
            }
        }
        atomicOr(&fl, flags);
        __syncthreads();
        if (t == 0) {
            unsigned int f = fl;
            int mode = 0;
            if (f & 8u)       mode = 3;
            else if (f & 1u)  mode = 0;
            else if (f & 16u) mode = 4;
            else if (f & 2u)  mode = 1;
            else if (f & 4u)  mode = 2;
            g_maskMode = mode;
        }
        return;
    }
    int idx = blockIdx.x * blockDim.x + threadIdx.x;
    if (idx < NC * NC) {
        int o = idx >> 7, c = idx & (NC - 1);
        float fs = fg[o] * rsqrtf(fv[o] + EPSF);
        float v = fw[o * NC + c] * fs;
        __half hi = __float2half_rn(v);
        g_Whi16[o * NC + c] = hi;
        g_Wlo16[o * NC + c] = __float2half_rn(v - __half2float(hi));
    }
    if (idx < NC) {
        int o = idx;
        float fs = fg[o] * rsqrtf(fv[o] + EPSF);
        g_fshift[o] = fb_[o] - fm[o] * fs;
        float ps = pg[o] * rsqrtf(pv[o] + EPSF);
        g_pshift[o] = pb_[o] - pm[o] * ps;
        g_pws[o * 3 + 0] = pw[o * 3 + 0] * ps;
        g_pws[o * 3 + 1] = pw[o * 3 + 1] * ps;
        g_pws[o * 3 + 2] = pw[o * 3 + 2] * ps;
    }
    if (idx < 3) {
        float es = eg[idx] * rsqrtf(ev[idx] + EPSF);
        g_escale[idx] = es;
        g_eshift[idx] = eb_[idx] - em[idx] * es;
    }
}

__global__ void convert_mask_kernel(const void* __restrict__ m) {
    int i = blockIdx.x * blockDim.x + threadIdx.x;
    if (i >= NB * NHW) return;
    int mode = g_maskMode;
    float v;
    if (mode == 0)      v = ((const float*)m)[i];
    else if (mode == 1) v = (float)((const unsigned char*)m)[i];
    else if (mode == 2) v = (float)((const int*)m)[i];
    else if (mode == 3) v = __bfloat162float(((const __nv_bfloat16*)m)[i]);
    else                v = __half2float(((const __half*)m)[i]);
    g_maskF[i] = (v != 0.0f) ? 1.0f : 0.0f;
}

// ---------------- pass 1: fp16 split tensor-core GEMM ------------------------
#define APITCH 24
#define BPITCH 136
#define SPITCH 66

__device__ __forceinline__ unsigned sptr(const void* p) {
    return (unsigned)__cvta_generic_to_shared(p);
}
__device__ __forceinline__ void ldsm4(unsigned& r0, unsigned& r1, unsigned& r2,
                                      unsigned& r3, unsigned a) {
    asm volatile("ldmatrix.sync.aligned.m8n8.x4.shared.b16 {%0,%1,%2,%3}, [%4];"
                 : "=r"(r0), "=r"(r1), "=r"(r2), "=r"(r3) : "r"(a));
}
__device__ __forceinline__ void ldsm4t(unsigned& r0, unsigned& r1, unsigned& r2,
                                       unsigned& r3, unsigned a) {
    asm volatile("ldmatrix.sync.aligned.m8n8.x4.trans.shared.b16 {%0,%1,%2,%3}, [%4];"
                 : "=r"(r0), "=r"(r1), "=r"(r2), "=r"(r3) : "r"(a));
}
__device__ __forceinline__ void mma16816(float* d, const unsigned* a, const unsigned* b) {
    asm volatile(
        "mma.sync.aligned.m16n8k16.row.col.f32.f16.f16.f32 "
        "{%0,%1,%2,%3}, {%4,%5,%6,%7}, {%8,%9}, {%0,%1,%2,%3};"
        : "+f"(d[0]), "+f"(d[1]), "+f"(d[2]), "+f"(d[3])
        : "r"(a[0]), "r"(a[1]), "r"(a[2]), "r"(a[3]), "r"(b[0]), "r"(b[1]));
}

__global__ void __launch_bounds__(256)
gemm_kernel(const float* __restrict__ feat) {
    __shared__ __align__(16) unsigned char smraw[41984];
    __half* sAh = (__half*)smraw;
    __half* sAl = sAh + 6144;
    __half* sBh = sAl + 6144;
    __half* sBl = sBh + 4352;

    const int b = blockIdx.y;
    const int ptile = blockIdx.x * 128;
    const int tid = threadIdx.x;
    const int lane = tid & 31, wid = tid >> 5;
    const int g = lane >> 2, tg = lane & 3;
    const int wm = wid & 1, wn = wid >> 1;

    const float* featB = feat + (size_t)b * NC * NHW + ptile;

    float acc[4][4][4];
#pragma unroll
    for (int mt = 0; mt < 4; mt++)
#pragma unroll
        for (int nt = 0; nt < 4; nt++)
#pragma unroll
            for (int i = 0; i < 4; i++) acc[mt][nt][i] = 0.0f;

    const int aRow = tid >> 1, aSeg = tid & 1;
    uint4 avh, avl;
    float4 bf0, bf1;

    const int aR = (lane & 7) + ((lane >> 3) & 1) * 8;
    const int aC = (lane >> 4) * 8;
    const int bK = (lane & 7) + ((lane >> 3) & 1) * 8;
    const int bC = (lane >> 4) * 8;

#define LOAD_CHUNK(kc)                                                              \
    do {                                                                            \
        avh = *(const uint4*)(g_Whi16 + aRow * NC + (kc) * 16 + aSeg * 8);          \
        avl = *(const uint4*)(g_Wlo16 + aRow * NC + (kc) * 16 + aSeg * 8);          \
        bf0 = *(const float4*)&featB[(size_t)((kc) * 16 + (tid >> 5)) * NHW + (tid & 31) * 4];            \
        bf1 = *(const float4*)&featB[(size_t)((kc) * 16 + ((tid + 256) >> 5)) * NHW + (tid & 31) * 4];    \
    } while (0)

#define STORE_CHUNK(buf)                                                            \
    do {                                                                            \
        *(uint4*)(sAh + (buf) * 3072 + aRow * APITCH + aSeg * 8) = avh;             \
        *(uint4*)(sAl + (buf) * 3072 + aRow * APITCH + aSeg * 8) = avl;             \
        float4 xs[2] = {bf0, bf1};                                                  \
        _Pragma("unroll")                                                           \
        for (int ii = 0; ii < 2; ii++) {                                            \
            int idx = tid + ii * 256;                                               \
            int kk = idx >> 5, p4 = idx & 31;                                       \
            float4 x = xs[ii];                                                      \
            __half hx = __float2half_rn(x.x), hy = __float2half_rn(x.y);            \
            __half hz = __float2half_rn(x.z), hw = __float2half_rn(x.w);            \
            __half lx = __float2half_rn(x.x - __half2float(hx));                    \
            __half ly = __float2half_rn(x.y - __half2float(hy));                    \
            __half lz = __float2half_rn(x.z - __half2float(hz));                    \
            __half lw = __float2half_rn(x.w - __half2float(hw));                    \
            __half* dh = sBh + (buf) * 2176 + kk * BPITCH + p4 * 4;                 \
            __half* dl = sBl + (buf) * 2176 + kk * BPITCH + p4 * 4;                 \
            *(__half2*)(dh)     = __halves2half2(hx, hy);                           \
            *(__half2*)(dh + 2) = __halves2half2(hz, hw);                           \
            *(__half2*)(dl)     = __halves2half2(lx, ly);                           \
            *(__half2*)(dl + 2) = __halves2half2(lz, lw);                           \
        }                                                                           \
    } while (0)

    LOAD_CHUNK(0);
    STORE_CHUNK(0);
    __syncthreads();

    for (int kc = 0; kc < 8; kc++) {
        const int buf = kc & 1;
        if (kc < 7) LOAD_CHUNK(kc + 1);

        unsigned ah[4][4], al[4][4], bh[2][4], bl[2][4];
#pragma unroll
        for (int mt = 0; mt < 4; mt++) {
            int m0 = wm * 64 + mt * 16;
            unsigned adr = sptr(sAh + buf * 3072 + (m0 + aR) * APITCH + aC);
            ldsm4(ah[mt][0], ah[mt][1], ah[mt][2], ah[mt][3], adr);
            unsigned adl = sptr(sAl + buf * 3072 + (m0 + aR) * APITCH + aC);
            ldsm4(al[mt][0], al[mt][1], al[mt][2], al[mt][3], adl);
        }
#pragma unroll
        for (int j = 0; j < 2; j++) {
            int n0 = wn * 32 + j * 16;
            unsigned adr = sptr(sBh + buf * 2176 + bK * BPITCH + n0 + bC);
            ldsm4t(bh[j][0], bh[j][1], bh[j][2], bh[j][3], adr);
            unsigned adl = sptr(sBl + buf * 2176 + bK * BPITCH + n0 + bC);
            ldsm4t(bl[j][0], bl[j][1], bl[j][2], bl[j][3], adl);
        }

#pragma unroll
        for (int mt = 0; mt < 4; mt++)
#pragma unroll
            for (int nt = 0; nt < 4; nt++) {
                int j = nt >> 1, s2 = (nt & 1) * 2;
                unsigned bhv[2] = {bh[j][s2], bh[j][s2 + 1]};
                unsigned blv[2] = {bl[j][s2], bl[j][s2 + 1]};
                mma16816(acc[mt][nt], ah[mt], bhv);
                mma16816(acc[mt][nt], al[mt], bhv);
                mma16816(acc[mt][nt], ah[mt], blv);
            }

        if (kc < 7) STORE_CHUNK(buf ^ 1);
        __syncthreads();
    }

    // ---- epilogue: transpose, fold BN/relu/mask, write fp16 B plane ---------
    float* S = (float*)smraw;
    const float* maskB = g_maskF + (size_t)b * NHW;

    for (int hf = 0; hf < 2; hf++) {
        __syncthreads();
        if ((wn >> 1) == hf) {
#pragma unroll
            for (int mt = 0; mt < 4; mt++) {
                int r0 = wm * 64 + mt * 16 + g;
#pragma unroll
                for (int nt = 0; nt < 4; nt++) {
                    int col = (wn & 1) * 32 + nt * 8 + 2 * tg;
                    S[r0 * SPITCH + col]     = acc[mt][nt][0];
                    S[r0 * SPITCH + col + 1] = acc[mt][nt][1];
                    S[(r0 + 8) * SPITCH + col]     = acc[mt][nt][2];
                    S[(r0 + 8) * SPITCH + col + 1] = acc[mt][nt][3];
                }
            }
        }
        __syncthreads();
#pragma unroll
        for (int i = 0; i < 8; i++) {
            int item = tid + i * 256;
            int px = item & 63, og = item >> 6;
            int p = ptile + hf * 64 + px;
            int o = og * 4;
            float t0 = fmaxf(S[(o + 0) * SPITCH + px] + g_fshift[o + 0], 0.f);
            float t1 = fmaxf(S[(o + 1) * SPITCH + px] + g_fshift[o + 1], 0.f);
            float t2 = fmaxf(S[(o + 2) * SPITCH + px] + g_fshift[o + 2], 0.f);
            float t3 = fmaxf(S[(o + 3) * SPITCH + px] + g_fshift[o + 3], 0.f);
            bool valid = (maskB[p] != 0.0f);
            float b0 = valid ? t0 : NEGF;   // NEGF -> -inf in fp16 (propagates)
            float b1 = valid ? t1 : NEGF;
            float b2 = valid ? t2 : NEGF;
            float b3 = valid ? t3 : NEGF;
            __half2 lo = __floats2half2_rn(b0, b1);
            __half2 hi = __floats2half2_rn(b2, b3);
            uint2 pk;
            pk.x = *(unsigned*)&lo;
            pk.y = *(unsigned*)&hi;
            g_arrBh[((size_t)b * 32 + og) * NHW + p] = pk;
        }
    }
}

// ---------------- pass 2: load-based separable maxpool (fp16 planes) ---------
#define HT 8

struct PWr {
    float w0[4], w1[4], w2[4], ps[4];
};

__device__ __forceinline__ float4 q_of(const PWr& c, float c0, float c1, float c2) {
    float4 q;
    q.x = fmaf(c.w0[0], c0, fmaf(c.w1[0], c1, c.w2[0] * c2));
    q.y = fmaf(c.w0[1], c0, fmaf(c.w1[1], c1, c.w2[1] * c2));
    q.z = fmaf(c.w0[2], c0, fmaf(c.w1[2], c1, c.w2[2] * c2));
    q.w = fmaf(c.w0[3], c0, fmaf(c.w1[3], c1, c.w2[3] * c2));
    return q;
}

__device__ __forceinline__ float4 ldB4(const uint2* __restrict__ p, int idx) {
    uint2 v = p[idx];
    float2 f0 = __half22float2(*(__half2*)&v.x);
    float2 f1 = __half22float2(*(__half2*)&v.y);
    return make_float4(f0.x, f0.y, f1.x, f1.y);
}

// Horizontal max3 of B and of A = B + ps + Q'; returns center Q' for reuse.
__device__ __forceinline__ void hrow3(int hh, int w,
                                      const uint2* __restrict__ pB,
                                      const float* __restrict__ cartB,
                                      const PWr& c,
                                      float4& ha, float4& hb, float4& hq) {
    const float4 NEG4 = make_float4(NEGF, NEGF, NEGF, NEGF);
    if ((unsigned)hh >= NH) {
        ha = NEG4; hb = NEG4;
        hq = make_float4(0.f, 0.f, 0.f, 0.f);
        return;
    }
    int idx = hh * NW + w;
    // center
    float4 b0 = ldB4(pB, idx);
    float4 q0 = q_of(c, cartB[idx], cartB[NHW + idx], cartB[2 * NHW + idx]);
    hq = q0;
    float4 a0;
    a0.x = b0.x + c.ps[0] + q0.x;
    a0.y = b0.y + c.ps[1] + q0.y;
    a0.z = b0.z + c.ps[2] + q0.z;
    a0.w = b0.w + c.ps[3] + q0.w;
    // left
    float4 aL = NEG4, bL = NEG4;
    if (w > 0) {
        float4 bm = ldB4(pB, idx - 1);
        float4 ql = q_of(c, cartB[idx - 1], cartB[NHW + idx - 1], cartB[2 * NHW + idx - 1]);
        bL = bm;
        aL.x = bm.x + c.ps[0] + ql.x;
        aL.y = bm.y + c.ps[1] + ql.y;
        aL.z = bm.z + c.ps[2] + ql.z;
        aL.w = bm.w + c.ps[3] + ql.w;
    }
    // right
    float4 aR = NEG4, bR = NEG4;
    if (w < NW - 1) {
        float4 bp = ldB4(pB, idx + 1);
        float4 qr = q_of(c, cartB[idx + 1], cartB[NHW + idx + 1], cartB[2 * NHW + idx + 1]);
        bR = bp;
        aR.x = bp.x + c.ps[0] + qr.x;
        aR.y = bp.y + c.ps[1] + qr.y;
        aR.z = bp.z + c.ps[2] + qr.z;
        aR.w = bp.w + c.ps[3] + qr.w;
    }
    ha.x = fmaxf(fmaxf(aL.x, a0.x), aR.x);
    ha.y = fmaxf(fmaxf(aL.y, a0.y), aR.y);
    ha.z = fmaxf(fmaxf(aL.z, a0.z), aR.z);
    ha.w = fmaxf(fmaxf(aL.w, a0.w), aR.w);
    hb.x = fmaxf(fmaxf(bL.x, b0.x), bR.x);
    hb.y = fmaxf(fmaxf(bL.y, b0.y), bR.y);
    hb.z = fmaxf(fmaxf(bL.z, b0.z), bR.z);
    hb.w = fmaxf(fmaxf(bL.w, b0.w), bR.w);
}

__global__ void __launch_bounds__(256, 4)
pool_kernel(const float* __restrict__ cart, float* __restrict__ out) {
    const int z = blockIdx.z;
    const int b = z >> 2;
    const int og = (z & 3) * 8 + (threadIdx.x >> 5);
    const int lane = threadIdx.x & 31;
    const int h0 = blockIdx.y * HT;
    const int w = blockIdx.x * 32 + lane;
    const int o = og * 4;

    const uint2* pB = g_arrBh + ((size_t)b * 32 + og) * NHW;
    float* outB = out + ((size_t)b * NC + o) * NHW;
    const float* cartB = cart + (size_t)b * 3 * NHW;

    PWr c;
#pragma unroll
    for (int j = 0; j < 4; j++) {
        c.w0[j] = g_pws[(o + j) * 3 + 0];
        c.w1[j] = g_pws[(o + j) * 3 + 1];
        c.w2[j] = g_pws[(o + j) * 3 + 2];
        c.ps[j] = g_pshift[o + j];
    }

    float4 mA, mB, cA, cB, cQ, nA, nB, nQ, dQ;
    hrow3(h0 - 1, w, pB, cartB, c, mA, mB, dQ);
    hrow3(h0,     w, pB, cartB, c, cA, cB, cQ);

#pragma unroll
    for (int r = 0; r < HT; r++) {
        int h = h0 + r;
        hrow3(h + 1, w, pB, cartB, c, nA, nB, nQ);
        int p = h * NW + w;

        float gx = fmaxf(fmaxf(fmaxf(fmaxf(mA.x, cA.x), nA.x) - cQ.x,
                               fmaxf(fmaxf(mB.x, cB.x), nB.x)), 0.f);
        float gy = fmaxf(fmaxf(fmaxf(fmaxf(mA.y, cA.y), nA.y) - cQ.y,
                               fmaxf(fmaxf(mB.y, cB.y), nB.y)), 0.f);
        float gz = fmaxf(fmaxf(fmaxf(fmaxf(mA.z, cA.z), nA.z) - cQ.z,
                               fmaxf(fmaxf(mB.z, cB.z), nB.z)), 0.f);
        float gw = fmaxf(fmaxf(fmaxf(fmaxf(mA.w, cA.w), nA.w) - cQ.w,
                               fmaxf(fmaxf(mB.w, cB.w), nB.w)), 0.f);

        outB[p] = gx;
        outB[NHW + p] = gy;
        outB[2 * NHW + p] = gz;
        outB[3 * NHW + p] = gw;

        mA = cA; cA = nA;
        mB = cB; cB = nB;
        cQ = nQ;
    }
}

// ---------------- pass 3: e2c residual (8-warp channel split) ----------------
__global__ void __launch_bounds__(256)
e2c_kernel(const float* __restrict__ cart, const float* __restrict__ ew,
           float* __restrict__ out) {
    __shared__ float4 red[8][3][32];
    const int lane = threadIdx.x & 31, wy = threadIdx.x >> 5;
    const int t = blockIdx.x * 32 + lane;
    const int b = t >> 13;
    const int p4 = (t & 8191) * 4;

    const float* geo = out + ((size_t)b * NC + wy * 16) * NHW + p4;
    float4 s0 = make_float4(0.f, 0.f, 0.f, 0.f), s1 = s0, s2 = s0;
#pragma unroll
    for (int c = 0; c < 16; c++) {
        float4 g4 = *(const float4*)&geo[(size_t)c * NHW];
        int cc = wy * 16 + c;
        float w0 = ew[cc], w1 = ew[NC + cc], w2 = ew[2 * NC + cc];
        s0.x += w0 * g4.x; s0.y += w0 * g4.y; s0.z += w0 * g4.z; s0.w += w0 * g4.w;
        s1.x += w1 * g4.x; s1.y += w1 * g4.y; s1.z += w1 * g4.z; s1.w += w1 * g4.w;
        s2.x += w2 * g4.x; s2.y += w2 * g4.y; s2.z += w2 * g4.z; s2.w += w2 * g4.w;
    }
    red[wy][0][lane] = s0;
    red[wy][1][lane] = s1;
    red[wy][2][lane] = s2;
    __syncthreads();

    if (wy < 3) {
        const int j = wy;
        float4 a = red[0][j][lane];
#pragma unroll
        for (int u = 1; u < 8; u++) {
            float4 v = red[u][j][lane];
            a.x += v.x; a.y += v.y; a.z += v.z; a.w += v.w;
        }
        float4 m4 = *(const float4*)&g_maskF[(size_t)b * NHW + p4];
        const float* cartB = cart + ((size_t)b * 3 + j) * NHW + p4;
        float4 cv = *(const float4*)cartB;
        float es = g_escale[j], eh = g_eshift[j];
        float4 r;
        r.x = cv.x + (es * a.x + eh) * m4.x;
        r.y = cv.y + (es * a.y + eh) * m4.y;
        r.z = cv.z + (es * a.z + eh) * m4.z;
        r.w = cv.w + (es * a.w + eh) * m4.w;
        *(float4*)&out[(size_t)NB * NC * NHW + ((size_t)b * 3 + j) * NHW + p4] = r;
    }
}

// ---------------- launch -----------------------------------------------------
extern "C" void kernel_launch(void* const* d_in, const int* in_sizes, int n_in,
                              void* d_out, int out_size) {
    const float* feat = (const float*)d_in[0];
    const float* cart = (const float*)d_in[1];
    const void*  mask = d_in[2];
    const float* pw = (const float*)d_in[3];
    const float* pg = (const float*)d_in[4];
    const float* pb = (const float*)d_in[5];
    const float* pm = (const float*)d_in[6];
    const float* pv = (const float*)d_in[7];
    const float* fw = (const float*)d_in[8];
    const float* fg = (const float*)d_in[9];
    const float* fbp = (const float*)d_in[10];
    const float* fm = (const float*)d_in[11];
    const float* fv = (const float*)d_in[12];
    const float* ew = (const float*)d_in[13];
    const float* eg = (const float*)d_in[14];
    const float* eb = (const float*)d_in[15];
    const float* em = (const float*)d_in[16];
    const float* ev = (const float*)d_in[17];

    prep_kernel<<<65, 256>>>(fw, fg, fbp, fm, fv, pw, pg, pb, pm, pv,
                             eg, eb, em, ev, (const unsigned int*)mask);
    convert_mask_kernel<<<(NB * NHW + 255) / 256, 256>>>(mask);

    dim3 g1(NHW / 128, NB);
    gemm_kernel<<<g1, 256>>>(feat);

    dim3 g2(NW / 32, NH / HT, NB * 4);
    pool_kernel<<<g2, 256>>>(cart, (float*)d_out);

    e2c_kernel<<<NB * NHW / 128, 256>>>(cart, ew, (float*)d_out);
}

// round 11
// speedup vs baseline: 1.4634x; 1.4634x over previous
#include <cuda_runtime.h>
#include <cuda_bf16.h>
#include <cuda_fp16.h>

#define NB   2
#define NC   128
#define NH   64
#define NW   512
#define NHW  32768
#define EPSF 1e-5f
#define NEGF (-1.0e30f)

// ---------------- scratch (device globals) ----------------------------------
__device__ float4 g_arrB[NB * 32 * NHW];  // maskfold(T)  [b][og][p]
__device__ __align__(16) __half g_Whi16[NC * NC];
__device__ __align__(16) __half g_Wlo16[NC * NC];
__device__ float  g_fshift[NC];
__device__ float  g_pws[NC * 3];
__device__ float  g_pshift[NC];
__device__ float  g_escale[4];
__device__ float  g_eshift[4];
__device__ float  g_maskF[NB * NHW];
__device__ int    g_maskMode;

// ---------------- prep + mask dtype detection (merged) -----------------------
__global__ void prep_kernel(const float* __restrict__ fw, const float* __restrict__ fg,
                            const float* __restrict__ fb_, const float* __restrict__ fm,
                            const float* __restrict__ fv, const float* __restrict__ pw,
                            const float* __restrict__ pg, const float* __restrict__ pb_,
                            const float* __restrict__ pm, const float* __restrict__ pv,
                            const float* __restrict__ eg, const float* __restrict__ eb_,
                            const float* __restrict__ em, const float* __restrict__ ev,
                            const unsigned int* __restrict__ mraw) {
    if (blockIdx.x == 64) {
        __shared__ unsigned int fl;
        int t = threadIdx.x;
        if (t == 0) fl = 0;
        __syncthreads();
        unsigned int flags = 0;
        for (int k = t; k < 1024; k += 256) {
            unsigned int x = mraw[k];
            if (x == 0u) continue;
            unsigned int lo = x & 0xFFFFu, hi = x >> 16;
            if (x == 0x3F800000u) flags |= 1u;
            bool blo = (lo == 0u || lo == 0x3F80u), bhi = (hi == 0u || hi == 0x3F80u);
            bool hlo = (lo == 0u || lo == 0x3C00u), hhi = (hi == 0u || hi == 0x3C00u);
            if (blo && bhi && x != 0x3F800000u) flags |= 8u;
            else if (hlo && hhi) flags |= 16u;
            else if ((x & 0xFEFEFEFEu) == 0u) {
                if (x & 0xFFFFFF00u) flags |= 2u;
                else flags |= 4u;
            }
        }
        atomicOr(&fl, flags);
        __syncthreads();
        if (t == 0) {
            unsigned int f = fl;
            int mode = 0;
            if (f & 8u)       mode = 3;
            else if (f & 1u)  mode = 0;
            else if (f & 16u) mode = 4;
            else if (f & 2u)  mode = 1;
            else if (f & 4u)  mode = 2;
            g_maskMode = mode;
        }
        return;
    }
    int idx = blockIdx.x * blockDim.x + threadIdx.x;
    if (idx < NC * NC) {
        int o = idx >> 7, c = idx & (NC - 1);
        float fs = fg[o] * rsqrtf(fv[o] + EPSF);
        float v = fw[o * NC + c] * fs;
        __half hi = __float2half_rn(v);
        g_Whi16[o * NC + c] = hi;
        g_Wlo16[o * NC + c] = __float2half_rn(v - __half2float(hi));
    }
    if (idx < NC) {
        int o = idx;
        float fs = fg[o] * rsqrtf(fv[o] + EPSF);
        g_fshift[o] = fb_[o] - fm[o] * fs;
        float ps = pg[o] * rsqrtf(pv[o] + EPSF);
        g_pshift[o] = pb_[o] - pm[o] * ps;
        g_pws[o * 3 + 0] = pw[o * 3 + 0] * ps;
        g_pws[o * 3 + 1] = pw[o * 3 + 1] * ps;
        g_pws[o * 3 + 2] = pw[o * 3 + 2] * ps;
    }
    if (idx < 3) {
        float es = eg[idx] * rsqrtf(ev[idx] + EPSF);
        g_escale[idx] = es;
        g_eshift[idx] = eb_[idx] - em[idx] * es;
    }
}

__global__ void convert_mask_kernel(const void* __restrict__ m) {
    int i = blockIdx.x * blockDim.x + threadIdx.x;
    if (i >= NB * NHW) return;
    int mode = g_maskMode;
    float v;
    if (mode == 0)      v = ((const float*)m)[i];
    else if (mode == 1) v = (float)((const unsigned char*)m)[i];
    else if (mode == 2) v = (float)((const int*)m)[i];
    else if (mode == 3) v = __bfloat162float(((const __nv_bfloat16*)m)[i]);
    else                v = __half2float(((const __half*)m)[i]);
    g_maskF[i] = (v != 0.0f) ? 1.0f : 0.0f;
}

// ---------------- pass 1: fp16 2-term tensor-core GEMM -----------------------
// T = W*feat with W split hi+lo fp16, feat cast to fp16 (single term).
// Error ~2^-11 relative on feat, randomized over K=128.
#define APITCH 24
#define BPITCH 136
#define SPITCH 66

__device__ __forceinline__ unsigned sptr(const void* p) {
    return (unsigned)__cvta_generic_to_shared(p);
}
__device__ __forceinline__ void ldsm4(unsigned& r0, unsigned& r1, unsigned& r2,
                                      unsigned& r3, unsigned a) {
    asm volatile("ldmatrix.sync.aligned.m8n8.x4.shared.b16 {%0,%1,%2,%3}, [%4];"
                 : "=r"(r0), "=r"(r1), "=r"(r2), "=r"(r3) : "r"(a));
}
__device__ __forceinline__ void ldsm4t(unsigned& r0, unsigned& r1, unsigned& r2,
                                       unsigned& r3, unsigned a) {
    asm volatile("ldmatrix.sync.aligned.m8n8.x4.trans.shared.b16 {%0,%1,%2,%3}, [%4];"
                 : "=r"(r0), "=r"(r1), "=r"(r2), "=r"(r3) : "r"(a));
}
__device__ __forceinline__ void mma16816(float* d, const unsigned* a, const unsigned* b) {
    asm volatile(
        "mma.sync.aligned.m16n8k16.row.col.f32.f16.f16.f32 "
        "{%0,%1,%2,%3}, {%4,%5,%6,%7}, {%8,%9}, {%0,%1,%2,%3};"
        : "+f"(d[0]), "+f"(d[1]), "+f"(d[2]), "+f"(d[3])
        : "r"(a[0]), "r"(a[1]), "r"(a[2]), "r"(a[3]), "r"(b[0]), "r"(b[1]));
}

__global__ void __launch_bounds__(256)
gemm_kernel(const float* __restrict__ feat) {
    __shared__ __align__(16) unsigned char smraw[33792];
    __half* sAh = (__half*)smraw;          // [2][128][24]
    __half* sAl = sAh + 6144;              // [2][128][24]
    __half* sBh = sAl + 6144;              // [2][16][136]

    const int b = blockIdx.y;
    const int ptile = blockIdx.x * 128;
    const int tid = threadIdx.x;
    const int lane = tid & 31, wid = tid >> 5;
    const int g = lane >> 2, tg = lane & 3;
    const int wm = wid & 1, wn = wid >> 1;

    const float* featB = feat + (size_t)b * NC * NHW + ptile;

    float acc[4][4][4];
#pragma unroll
    for (int mt = 0; mt < 4; mt++)
#pragma unroll
        for (int nt = 0; nt < 4; nt++)
#pragma unroll
            for (int i = 0; i < 4; i++) acc[mt][nt][i] = 0.0f;

    const int aRow = tid >> 1, aSeg = tid & 1;
    uint4 avh, avl;
    float4 bf0, bf1;

    const int aR = (lane & 7) + ((lane >> 3) & 1) * 8;
    const int aC = (lane >> 4) * 8;
    const int bK = (lane & 7) + ((lane >> 3) & 1) * 8;
    const int bC = (lane >> 4) * 8;

#define LOAD_CHUNK(kc)                                                              \
    do {                                                                            \
        avh = *(const uint4*)(g_Whi16 + aRow * NC + (kc) * 16 + aSeg * 8);          \
        avl = *(const uint4*)(g_Wlo16 + aRow * NC + (kc) * 16 + aSeg * 8);          \
        bf0 = *(const float4*)&featB[(size_t)((kc) * 16 + (tid >> 5)) * NHW + (tid & 31) * 4];            \
        bf1 = *(const float4*)&featB[(size_t)((kc) * 16 + ((tid + 256) >> 5)) * NHW + (tid & 31) * 4];    \
    } while (0)

#define STORE_CHUNK(buf)                                                            \
    do {                                                                            \
        *(uint4*)(sAh + (buf) * 3072 + aRow * APITCH + aSeg * 8) = avh;             \
        *(uint4*)(sAl + (buf) * 3072 + aRow * APITCH + aSeg * 8) = avl;             \
        float4 xs[2] = {bf0, bf1};                                                  \
        _Pragma("unroll")                                                           \
        for (int ii = 0; ii < 2; ii++) {                                            \
            int idx = tid + ii * 256;                                               \
            int kk = idx >> 5, p4 = idx & 31;                                       \
            float4 x = xs[ii];                                                      \
            __half2 h01 = __floats2half2_rn(x.x, x.y);                              \
            __half2 h23 = __floats2half2_rn(x.z, x.w);                              \
            __half* dh = sBh + (buf) * 2176 + kk * BPITCH + p4 * 4;                 \
            *(__half2*)(dh)     = h01;                                              \
            *(__half2*)(dh + 2) = h23;                                              \
        }                                                                           \
    } while (0)

    LOAD_CHUNK(0);
    STORE_CHUNK(0);
    __syncthreads();

    for (int kc = 0; kc < 8; kc++) {
        const int buf = kc & 1;
        if (kc < 7) LOAD_CHUNK(kc + 1);

        unsigned ah[4][4], al[4][4], bh[2][4];
#pragma unroll
        for (int mt = 0; mt < 4; mt++) {
            int m0 = wm * 64 + mt * 16;
            unsigned adr = sptr(sAh + buf * 3072 + (m0 + aR) * APITCH + aC);
            ldsm4(ah[mt][0], ah[mt][1], ah[mt][2], ah[mt][3], adr);
            unsigned adl = sptr(sAl + buf * 3072 + (m0 + aR) * APITCH + aC);
            ldsm4(al[mt][0], al[mt][1], al[mt][2], al[mt][3], adl);
        }
#pragma unroll
        for (int j = 0; j < 2; j++) {
            int n0 = wn * 32 + j * 16;
            unsigned adr = sptr(sBh + buf * 2176 + bK * BPITCH + n0 + bC);
            ldsm4t(bh[j][0], bh[j][1], bh[j][2], bh[j][3], adr);
        }

#pragma unroll
        for (int mt = 0; mt < 4; mt++)
#pragma unroll
            for (int nt = 0; nt < 4; nt++) {
                int j = nt >> 1, s2 = (nt & 1) * 2;
                unsigned bhv[2] = {bh[j][s2], bh[j][s2 + 1]};
                mma16816(acc[mt][nt], ah[mt], bhv);
                mma16816(acc[mt][nt], al[mt], bhv);
            }

        if (kc < 7) STORE_CHUNK(buf ^ 1);
        __syncthreads();
    }

    // ---- epilogue: transpose, fold BN/relu/mask, write fp32 B plane ---------
    float* S = (float*)smraw;
    const float* maskB = g_maskF + (size_t)b * NHW;

    for (int hf = 0; hf < 2; hf++) {
        __syncthreads();
        if ((wn >> 1) == hf) {
#pragma unroll
            for (int mt = 0; mt < 4; mt++) {
                int r0 = wm * 64 + mt * 16 + g;
#pragma unroll
                for (int nt = 0; nt < 4; nt++) {
                    int col = (wn & 1) * 32 + nt * 8 + 2 * tg;
                    S[r0 * SPITCH + col]     = acc[mt][nt][0];
                    S[r0 * SPITCH + col + 1] = acc[mt][nt][1];
                    S[(r0 + 8) * SPITCH + col]     = acc[mt][nt][2];
                    S[(r0 + 8) * SPITCH + col + 1] = acc[mt][nt][3];
                }
            }
        }
        __syncthreads();
#pragma unroll
        for (int i = 0; i < 8; i++) {
            int item = tid + i * 256;
            int px = item & 63, og = item >> 6;
            int p = ptile + hf * 64 + px;
            int o = og * 4;
            float t0 = fmaxf(S[(o + 0) * SPITCH + px] + g_fshift[o + 0], 0.f);
            float t1 = fmaxf(S[(o + 1) * SPITCH + px] + g_fshift[o + 1], 0.f);
            float t2 = fmaxf(S[(o + 2) * SPITCH + px] + g_fshift[o + 2], 0.f);
            float t3 = fmaxf(S[(o + 3) * SPITCH + px] + g_fshift[o + 3], 0.f);
            bool valid = (maskB[p] != 0.0f);
            float4 B4;
            B4.x = valid ? t0 : NEGF;
            B4.y = valid ? t1 : NEGF;
            B4.z = valid ? t2 : NEGF;
            B4.w = valid ? t3 : NEGF;
            g_arrB[((size_t)b * 32 + og) * NHW + p] = B4;
        }
    }
}

// ---------------- pass 2: load-based separable maxpool (fp32, occ 4) ---------
#define HT 16

struct PWr {
    float w0[4], w1[4], w2[4], ps[4];
};

__device__ __forceinline__ float4 q_of(const PWr& c, float c0, float c1, float c2) {
    float4 q;
    q.x = fmaf(c.w0[0], c0, fmaf(c.w1[0], c1, c.w2[0] * c2));
    q.y = fmaf(c.w0[1], c0, fmaf(c.w1[1], c1, c.w2[1] * c2));
    q.z = fmaf(c.w0[2], c0, fmaf(c.w1[2], c1, c.w2[2] * c2));
    q.w = fmaf(c.w0[3], c0, fmaf(c.w1[3], c1, c.w2[3] * c2));
    return q;
}

__device__ __forceinline__ void hrow3(int hh, int w,
                                      const float4* __restrict__ pB,
                                      const float* __restrict__ cartB,
                                      const PWr& c,
                                      float4& ha, float4& hb, float4& hq) {
    const float4 NEG4 = make_float4(NEGF, NEGF, NEGF, NEGF);
    if ((unsigned)hh >= NH) {
        ha = NEG4; hb = NEG4;
        hq = make_float4(0.f, 0.f, 0.f, 0.f);
        return;
    }
    int idx = hh * NW + w;
    float4 b0 = pB[idx];
    float4 q0 = q_of(c, cartB[idx], cartB[NHW + idx], cartB[2 * NHW + idx]);
    hq = q0;
    float4 a0;
    a0.x = b0.x + c.ps[0] + q0.x;
    a0.y = b0.y + c.ps[1] + q0.y;
    a0.z = b0.z + c.ps[2] + q0.z;
    a0.w = b0.w + c.ps[3] + q0.w;
    float4 aL = NEG4, bL = NEG4;
    if (w > 0) {
        float4 bm = pB[idx - 1];
        float4 ql = q_of(c, cartB[idx - 1], cartB[NHW + idx - 1], cartB[2 * NHW + idx - 1]);
        bL = bm;
        aL.x = bm.x + c.ps[0] + ql.x;
        aL.y = bm.y + c.ps[1] + ql.y;
        aL.z = bm.z + c.ps[2] + ql.z;
        aL.w = bm.w + c.ps[3] + ql.w;
    }
    float4 aR = NEG4, bR = NEG4;
    if (w < NW - 1) {
        float4 bp = pB[idx + 1];
        float4 qr = q_of(c, cartB[idx + 1], cartB[NHW + idx + 1], cartB[2 * NHW + idx + 1]);
        bR = bp;
        aR.x = bp.x + c.ps[0] + qr.x;
        aR.y = bp.y + c.ps[1] + qr.y;
        aR.z = bp.z + c.ps[2] + qr.z;
        aR.w = bp.w + c.ps[3] + qr.w;
    }
    ha.x = fmaxf(fmaxf(aL.x, a0.x), aR.x);
    ha.y = fmaxf(fmaxf(aL.y, a0.y), aR.y);
    ha.z = fmaxf(fmaxf(aL.z, a0.z), aR.z);
    ha.w = fmaxf(fmaxf(aL.w, a0.w), aR.w);
    hb.x = fmaxf(fmaxf(bL.x, b0.x), bR.x);
    hb.y = fmaxf(fmaxf(bL.y, b0.y), bR.y);
    hb.z = fmaxf(fmaxf(bL.z, b0.z), bR.z);
    hb.w = fmaxf(fmaxf(bL.w, b0.w), bR.w);
}

__global__ void __launch_bounds__(256, 4)
pool_kernel(const float* __restrict__ cart, float* __restrict__ out) {
    const int z = blockIdx.z;
    const int b = z >> 2;
    const int og = (z & 3) * 8 + (threadIdx.x >> 5);
    const int lane = threadIdx.x & 31;
    const int h0 = blockIdx.y * HT;
    const int w = blockIdx.x * 32 + lane;
    const int o = og * 4;

    const float4* pB = g_arrB + ((size_t)b * 32 + og) * NHW;
    float* outB = out + ((size_t)b * NC + o) * NHW;
    const float* cartB = cart + (size_t)b * 3 * NHW;

    PWr c;
#pragma unroll
    for (int j = 0; j < 4; j++) {
        c.w0[j] = g_pws[(o + j) * 3 + 0];
        c.w1[j] = g_pws[(o + j) * 3 + 1];
        c.w2[j] = g_pws[(o + j) * 3 + 2];
        c.ps[j] = g_pshift[o + j];
    }

    float4 mA, mB, cA, cB, cQ, nA, nB, nQ, dQ;
    hrow3(h0 - 1, w, pB, cartB, c, mA, mB, dQ);
    hrow3(h0,     w, pB, cartB, c, cA, cB, cQ);

    for (int r = 0; r < HT; r++) {
        int h = h0 + r;
        hrow3(h + 1, w, pB, cartB, c, nA, nB, nQ);
        int p = h * NW + w;

        float gx = fmaxf(fmaxf(fmaxf(fmaxf(mA.x, cA.x), nA.x) - cQ.x,
                               fmaxf(fmaxf(mB.x, cB.x), nB.x)), 0.f);
        float gy = fmaxf(fmaxf(fmaxf(fmaxf(mA.y, cA.y), nA.y) - cQ.y,
                               fmaxf(fmaxf(mB.y, cB.y), nB.y)), 0.f);
        float gz = fmaxf(fmaxf(fmaxf(fmaxf(mA.z, cA.z), nA.z) - cQ.z,
                               fmaxf(fmaxf(mB.z, cB.z), nB.z)), 0.f);
        float gw = fmaxf(fmaxf(fmaxf(fmaxf(mA.w, cA.w), nA.w) - cQ.w,
                               fmaxf(fmaxf(mB.w, cB.w), nB.w)), 0.f);

        outB[p] = gx;
        outB[NHW + p] = gy;
        outB[2 * NHW + p] = gz;
        outB[3 * NHW + p] = gw;

        mA = cA; cA = nA;
        mB = cB; cB = nB;
        cQ = nQ;
    }
}

// ---------------- pass 3: e2c residual (8-warp channel split) ----------------
__global__ void __launch_bounds__(256)
e2c_kernel(const float* __restrict__ cart, const float* __restrict__ ew,
           float* __restrict__ out) {
    __shared__ float4 red[8][3][32];
    const int lane = threadIdx.x & 31, wy = threadIdx.x >> 5;
    const int t = blockIdx.x * 32 + lane;
    const int b = t >> 13;
    const int p4 = (t & 8191) * 4;

    const float* geo = out + ((size_t)b * NC + wy * 16) * NHW + p4;
    float4 s0 = make_float4(0.f, 0.f, 0.f, 0.f), s1 = s0, s2 = s0;
#pragma unroll
    for (int c = 0; c < 16; c++) {
        float4 g4 = *(const float4*)&geo[(size_t)c * NHW];
        int cc = wy * 16 + c;
        float w0 = ew[cc], w1 = ew[NC + cc], w2 = ew[2 * NC + cc];
        s0.x += w0 * g4.x; s0.y += w0 * g4.y; s0.z += w0 * g4.z; s0.w += w0 * g4.w;
        s1.x += w1 * g4.x; s1.y += w1 * g4.y; s1.z += w1 * g4.z; s1.w += w1 * g4.w;
        s2.x += w2 * g4.x; s2.y += w2 * g4.y; s2.z += w2 * g4.z; s2.w += w2 * g4.w;
    }
    red[wy][0][lane] = s0;
    red[wy][1][lane] = s1;
    red[wy][2][lane] = s2;
    __syncthreads();

    if (wy < 3) {
        const int j = wy;
        float4 a = red[0][j][lane];
#pragma unroll
        for (int u = 1; u < 8; u++) {
            float4 v = red[u][j][lane];
            a.x += v.x; a.y += v.y; a.z += v.z; a.w += v.w;
        }
        float4 m4 = *(const float4*)&g_maskF[(size_t)b * NHW + p4];
        const float* cartB = cart + ((size_t)b * 3 + j) * NHW + p4;
        float4 cv = *(const float4*)cartB;
        float es = g_escale[j], eh = g_eshift[j];
        float4 r;
        r.x = cv.x + (es * a.x + eh) * m4.x;
        r.y = cv.y + (es * a.y + eh) * m4.y;
        r.z = cv.z + (es * a.z + eh) * m4.z;
        r.w = cv.w + (es * a.w + eh) * m4.w;
        *(float4*)&out[(size_t)NB * NC * NHW + ((size_t)b * 3 + j) * NHW + p4] = r;
    }
}

// ---------------- launch -----------------------------------------------------
extern "C" void kernel_launch(void* const* d_in, const int* in_sizes, int n_in,
                              void* d_out, int out_size) {
    const float* feat = (const float*)d_in[0];
    const float* cart = (const float*)d_in[1];
    const void*  mask = d_in[2];
    const float* pw = (const float*)d_in[3];
    const float* pg = (const float*)d_in[4];
    const float* pb = (const float*)d_in[5];
    const float* pm = (const float*)d_in[6];
    const float* pv = (const float*)d_in[7];
    const float* fw = (const float*)d_in[8];
    const float* fg = (const float*)d_in[9];
    const float* fbp = (const float*)d_in[10];
    const float* fm = (const float*)d_in[11];
    const float* fv = (const float*)d_in[12];
    const float* ew = (const float*)d_in[13];
    const float* eg = (const float*)d_in[14];
    const float* eb = (const float*)d_in[15];
    const float* em = (const float*)d_in[16];
    const float* ev = (const float*)d_in[17];

    prep_kernel<<<65, 256>>>(fw, fg, fbp, fm, fv, pw, pg, pb, pm, pv,
                             eg, eb, em, ev, (const unsigned int*)mask);
    convert_mask_kernel<<<(NB * NHW + 255) / 256, 256>>>(mask);

    dim3 g1(NHW / 128, NB);
    gemm_kernel<<<g1, 256>>>(feat);

    dim3 g2(NW / 32, NH / HT, NB * 4);
    pool_kernel<<<g2, 256>>>(cart, (float*)d_out);

    e2c_kernel<<<NB * NHW / 128, 256>>>(cart, ew, (float*)d_out);
}